// round 13
// baseline (speedup 1.0000x reference)
#include <cuda_runtime.h>
#include <cuda_fp16.h>

#define TSTEPS 2048
#define HID    2048
#define INP    1024
#define NOUT   512
#define ZLEN   (HID + INP)
#define NCTA   147
#define JPER   14
#define GSTRIDE (NCTA * 56)                  /* 8232 floats per timestep */

#define SRED_OFF   (56 * 2048 * 2)           /* 229376 : sRed[8][64] f32 */
#define SMEM_TOTAL (SRED_OFF + 2048)         /* 231424 <= 232448 */

__device__ __align__(256) float  d_G2[(size_t)TSTEPS * GSTRIDE];
__device__ __align__(256) __half d_h16[(size_t)TSTEPS * HID];   /* h history, fp16 */
__device__ unsigned d_bar;

__device__ __forceinline__ unsigned packh2(float a, float b) {
    __half2 h = __floats2half2_rn(a, b);
    return *(unsigned*)&h;
}
__device__ __forceinline__ unsigned long long packf2(float lo, float hi) {
    unsigned long long r;
    asm("mov.b64 %0, {%1, %2};" : "=l"(r) : "f"(lo), "f"(hi));
    return r;
}
__device__ __forceinline__ void unpackf2(unsigned long long v, float &lo, float &hi) {
    asm("mov.b64 {%0, %1}, %2;" : "=f"(lo), "=f"(hi) : "l"(v));
}
__device__ __forceinline__ unsigned long long addf32x2(unsigned long long a,
                                                       unsigned long long b) {
    unsigned long long r;
    asm("add.rn.f32x2 %0, %1, %2;" : "=l"(r) : "l"(a), "l"(b));
    return r;
}
__device__ __forceinline__ float sigmoidf_(float x) { return 1.0f / (1.0f + __expf(-x)); }
__device__ __forceinline__ float tanhf_(float x) {
    float e = __expf(2.0f * x); return 1.0f - 2.0f / (e + 1.0f);
}

// ---------------- GEMM: x-part preactivations, transposed output layout -------
// d_G2[t*GSTRIDE + bid*56 + jj*4 + g] = W_g[j, H:] . X[t] + b_g[j],  j = bid*14+jj
__global__ __launch_bounds__(256) void gemm_xpart(
    const float* __restrict__ Wf, const float* __restrict__ Wi,
    const float* __restrict__ Wc, const float* __restrict__ Wo,
    const float* __restrict__ bf, const float* __restrict__ bi,
    const float* __restrict__ bc, const float* __restrict__ bo,
    const float* __restrict__ X)
{
    __shared__ float As[16][132];
    __shared__ float Bs[16][132];
    const int bx = blockIdx.x, by = blockIdx.y;
    const int g = by >> 4, jb2 = (by & 15) << 7;
    const float* W  = (g == 0) ? Wf : (g == 1) ? Wi : (g == 2) ? Wc : Wo;
    const float* bb = (g == 0) ? bf : (g == 1) ? bi : (g == 2) ? bc : bo;
    const int tid = threadIdx.x, tx = tid & 15, ty = tid >> 4;
    float acc[8][8];
#pragma unroll
    for (int i = 0; i < 8; ++i)
#pragma unroll
        for (int j = 0; j < 8; ++j) acc[i][j] = 0.0f;
    for (int k0 = 0; k0 < INP; k0 += 16) {
#pragma unroll
        for (int i = 0; i < 2; ++i) {
            int f = tid + i * 256, row = f >> 2, kk = (f & 3) << 2;
            float4 v = *(const float4*)(W + (size_t)(jb2 + row) * ZLEN + HID + k0 + kk);
            As[kk][row] = v.x; As[kk+1][row] = v.y; As[kk+2][row] = v.z; As[kk+3][row] = v.w;
            float4 u = *(const float4*)(X + (size_t)((bx << 7) + row) * INP + k0 + kk);
            Bs[kk][row] = u.x; Bs[kk+1][row] = u.y; Bs[kk+2][row] = u.z; Bs[kk+3][row] = u.w;
        }
        __syncthreads();
#pragma unroll
        for (int k = 0; k < 16; ++k) {
            float a[8], b[8];
            *(float4*)&a[0] = *(const float4*)&As[k][ty*8];
            *(float4*)&a[4] = *(const float4*)&As[k][ty*8+4];
            *(float4*)&b[0] = *(const float4*)&Bs[k][tx*8];
            *(float4*)&b[4] = *(const float4*)&Bs[k][tx*8+4];
#pragma unroll
            for (int ii = 0; ii < 8; ++ii)
#pragma unroll
                for (int jj = 0; jj < 8; ++jj)
                    acc[ii][jj] = fmaf(a[ii], b[jj], acc[ii][jj]);
        }
        __syncthreads();
    }
#pragma unroll
    for (int ii = 0; ii < 8; ++ii) {
        const int j = jb2 + ty * 8 + ii;
        const float bv = __ldg(bb + j);
        const int bidr = j / JPER;
        const int jj   = j - bidr * JPER;
        const int base = bidr * 56 + jj * 4 + g;
#pragma unroll
        for (int q = 0; q < 8; ++q) {
            int t = (bx << 7) + tx * 8 + q;
            d_G2[(size_t)t * GSTRIDE + base] = acc[ii][q] + bv;
        }
    }
}

// ---------------- persistent recurrent kernel --------------------------------
// 147 CTAs x 1024. kg = wid&7 (256-wide k slice), rg = wid>>3 (14 rows + 1 y).
// Barrier: grid.sync pattern — lanes store d_h16, __syncwarp (warp-scope
// fence), then lane 0 does ONE red.release.gpu.add(1). 147 arrivals/step
// (avoids the 0.854 cyc/lane single-address RMW drain of per-lane arrives).
// Poll target = t*147.
__global__ void __launch_bounds__(1024, 1) lstm_recurrent(
    const float* __restrict__ Wf, const float* __restrict__ Wi,
    const float* __restrict__ Wc, const float* __restrict__ Wo,
    const float* __restrict__ Wy, const float* __restrict__ by,
    float* __restrict__ out)
{
    extern __shared__ char smem[];
    __half* sW   = (__half*)smem;
    float*  sRed = (float*)(smem + SRED_OFF);     // [kg][64]

    const int tid = threadIdx.x, wid = tid >> 5, lane = tid & 31;
    const int kg = wid & 7, rg = wid >> 3;
    const int rbase = rg * JPER;
    const int bid = blockIdx.x, jb = bid * JPER;
    int njj = HID - jb; njj = njj < 0 ? 0 : (njj > JPER ? JPER : njj);
    float* out_y = out;
    float* out_h = out + (size_t)TSTEPS * NOUT;
    unsigned* barp = &d_bar;

    // gate weights -> SMEM fp16 (56 rows x 2048 halfs)
    for (int c = tid; c < 56 * 256; c += 1024) {
        int gr = c >> 8;
        int k8 = (c & 255) << 3;
        int jj = gr >> 2, g = gr & 3;
        uint4 u = {0u, 0u, 0u, 0u};
        if (jj < njj) {
            const float* W = (g == 0) ? Wf : (g == 1) ? Wi : (g == 2) ? Wc : Wo;
            const float* p = W + (size_t)(jb + jj) * ZLEN + k8;
            float4 v0 = *(const float4*)p;
            float4 v1 = *(const float4*)(p + 4);
            u.x = packh2(v0.x, v0.y); u.y = packh2(v0.z, v0.w);
            u.z = packh2(v1.x, v1.y); u.w = packh2(v1.z, v1.w);
        }
        *(uint4*)(sW + gr * 2048 + k8) = u;
    }

    // y-row weights -> registers (row bid*4 + rg), fp16
    __half2 wy2[4];
    {
        unsigned z = 0u;
        wy2[0] = *(__half2*)&z; wy2[1] = *(__half2*)&z;
        wy2[2] = *(__half2*)&z; wy2[3] = *(__half2*)&z;
    }
    if (bid < 128) {
        const float* p = Wy + (size_t)(bid * 4 + rg) * HID + kg * 256 + lane * 8;
        float4 a = __ldg((const float4*)p);
        float4 b = __ldg((const float4*)(p + 4));
        unsigned t0 = packh2(a.x, a.y), t1 = packh2(a.z, a.w);
        unsigned t2 = packh2(b.x, b.y), t3 = packh2(b.z, b.w);
        wy2[0] = *(__half2*)&t0; wy2[1] = *(__half2*)&t1;
        wy2[2] = *(__half2*)&t2; wy2[3] = *(__half2*)&t3;
    }

    float c_st = 0.0f;                       // warp 0, lane = jj
    float byv = 0.0f;
    if (wid == 0 && lane >= 16 && lane < 20 && bid < 128)
        byv = __ldg(by + bid * 4 + (lane - 16));

    for (int t = 0; t <= TSTEPS; ++t) {
        if (t > 0 && wid == 0 && lane == 0) {     // single poller per CTA
            const unsigned target = (unsigned)t * (unsigned)NCTA;
            unsigned v;
            do {
                asm volatile("ld.acquire.gpu.global.u32 %0, [%1];"
                             : "=r"(v) : "l"(barp) : "memory");
            } while (v < target);
        }
        __syncthreads();                          // S1: release CTA; orders sRed WAR

        // warp 0: prefetch this step's G early (long latency cover)
        float4 gv = {0.f, 0.f, 0.f, 0.f};
        if (wid == 0 && lane < JPER && t < TSTEPS)
            gv = __ldcg((const float4*)(d_G2 + (size_t)t * GSTRIDE + bid * 56 + lane * 4));

        // h(t-1) slice -> half2 regs: one LDG.128 from fp16 history
        __half2 h2[4];
        if (t > 0) {
            uint4 hv = __ldcg((const uint4*)(d_h16 + (size_t)(t - 1) * HID + kg * 256 + lane * 8));
            h2[0] = *(__half2*)&hv.x; h2[1] = *(__half2*)&hv.y;
            h2[2] = *(__half2*)&hv.z; h2[3] = *(__half2*)&hv.w;
        } else {
            unsigned z = 0u;
            h2[0] = *(__half2*)&z; h2[1] = *(__half2*)&z;
            h2[2] = *(__half2*)&z; h2[3] = *(__half2*)&z;
        }

        // batch A: gate rows rbase .. rbase+7
        {
            float s[8];
#pragma unroll
            for (int r = 0; r < 8; ++r) {
                uint4 wv = *(const uint4*)(sW + (rbase + r) * 2048 + kg * 256 + lane * 8);
                __half2 acc = __hmul2(*(__half2*)&wv.x, h2[0]);
                acc = __hfma2(*(__half2*)&wv.y, h2[1], acc);
                acc = __hfma2(*(__half2*)&wv.z, h2[2], acc);
                acc = __hfma2(*(__half2*)&wv.w, h2[3], acc);
                float2 f = __half22float2(acc);
                s[r] = f.x + f.y;
            }
            unsigned long long v0 = packf2(s[0], s[1]), v1 = packf2(s[2], s[3]);
            unsigned long long v2 = packf2(s[4], s[5]), v3 = packf2(s[6], s[7]);
#pragma unroll
            for (int off = 16; off > 0; off >>= 1) {
                v0 = addf32x2(v0, __shfl_xor_sync(0xFFFFFFFFu, v0, off));
                v1 = addf32x2(v1, __shfl_xor_sync(0xFFFFFFFFu, v1, off));
                v2 = addf32x2(v2, __shfl_xor_sync(0xFFFFFFFFu, v2, off));
                v3 = addf32x2(v3, __shfl_xor_sync(0xFFFFFFFFu, v3, off));
            }
            if (lane == 0) {
                unsigned long long* dst = (unsigned long long*)(sRed + kg * 64 + rbase);
                dst[0] = v0; dst[1] = v1; dst[2] = v2; dst[3] = v3;
            }
        }
        // batch B: gate rows rbase+8 .. rbase+13, plus y row
        {
            float s[8];
#pragma unroll
            for (int r = 0; r < 6; ++r) {
                uint4 wv = *(const uint4*)(sW + (rbase + 8 + r) * 2048 + kg * 256 + lane * 8);
                __half2 acc = __hmul2(*(__half2*)&wv.x, h2[0]);
                acc = __hfma2(*(__half2*)&wv.y, h2[1], acc);
                acc = __hfma2(*(__half2*)&wv.z, h2[2], acc);
                acc = __hfma2(*(__half2*)&wv.w, h2[3], acc);
                float2 f = __half22float2(acc);
                s[r] = f.x + f.y;
            }
            {
                __half2 acc = __hmul2(wy2[0], h2[0]);
                acc = __hfma2(wy2[1], h2[1], acc);
                acc = __hfma2(wy2[2], h2[2], acc);
                acc = __hfma2(wy2[3], h2[3], acc);
                float2 f = __half22float2(acc);
                s[6] = f.x + f.y;
            }
            s[7] = 0.0f;
            unsigned long long v0 = packf2(s[0], s[1]), v1 = packf2(s[2], s[3]);
            unsigned long long v2 = packf2(s[4], s[5]), v3 = packf2(s[6], s[7]);
#pragma unroll
            for (int off = 16; off > 0; off >>= 1) {
                v0 = addf32x2(v0, __shfl_xor_sync(0xFFFFFFFFu, v0, off));
                v1 = addf32x2(v1, __shfl_xor_sync(0xFFFFFFFFu, v1, off));
                v2 = addf32x2(v2, __shfl_xor_sync(0xFFFFFFFFu, v2, off));
                v3 = addf32x2(v3, __shfl_xor_sync(0xFFFFFFFFu, v3, off));
            }
            if (lane == 0) {
                unsigned long long* dst = (unsigned long long*)(sRed + kg * 64 + rbase + 8);
                dst[0] = v0; dst[1] = v1; dst[2] = v2;
                float lo, hi;
                unpackf2(v3, lo, hi);
                sRed[kg * 64 + 56 + rg] = lo;
            }
        }

        __syncthreads();                          // S2

        if (wid == 0) {
            if (t < TSTEPS) {
                float hv = 0.0f;
                const bool act = (lane < njj);
                if (act) {
                    float4 a = *(const float4*)(sRed + 0 * 64 + lane * 4);
#pragma unroll
                    for (int k2 = 1; k2 < 8; ++k2) {
                        float4 b = *(const float4*)(sRed + k2 * 64 + lane * 4);
                        a.x += b.x; a.y += b.y; a.z += b.z; a.w += b.w;
                    }
                    a.x += gv.x; a.y += gv.y; a.z += gv.z; a.w += gv.w;
                    float fg = sigmoidf_(a.x);
                    float ig = sigmoidf_(a.y);
                    float cc = tanhf_(a.z);
                    float og = sigmoidf_(a.w);
                    c_st = fg * c_st + ig * cc;
                    hv = og * tanhf_(c_st);
                    d_h16[(size_t)t * HID + jb + lane] = __float2half(hv); // exchange FIRST
                }
                __syncwarp();                     // warp-scope fence: order lane stores
                if (lane == 0)                    // ONE arrival per CTA
                    asm volatile("red.release.gpu.global.add.u32 [%0], %1;"
                                 :: "l"(barp), "r"(1u) : "memory");
                if (act)
                    out_h[(size_t)t * HID + jb + lane] = hv;   // fp32 output, off-path
            }
            // y output off the critical path (after publish)
            if (t >= 1 && bid < 128 && lane >= 16 && lane < 20) {
                float s = 0.0f;
#pragma unroll
                for (int k2 = 0; k2 < 8; ++k2) s += sRed[k2 * 64 + 56 + (lane - 16)];
                out_y[(size_t)(t - 1) * NOUT + bid * 4 + (lane - 16)] = s + byv;
            }
        }
    }
}

extern "C" void kernel_launch(void* const* d_in, const int* in_sizes, int n_in,
                              void* d_out, int out_size) {
    (void)in_sizes; (void)n_in; (void)out_size;
    const float* X  = (const float*)d_in[0];
    const float* Wf = (const float*)d_in[1];
    const float* bf = (const float*)d_in[2];
    const float* Wi = (const float*)d_in[3];
    const float* bi = (const float*)d_in[4];
    const float* Wc = (const float*)d_in[5];
    const float* bc = (const float*)d_in[6];
    const float* Wo = (const float*)d_in[7];
    const float* bo = (const float*)d_in[8];
    const float* Wy = (const float*)d_in[9];
    const float* by = (const float*)d_in[10];
    float* out = (float*)d_out;

    cudaFuncSetAttribute(lstm_recurrent,
                         cudaFuncAttributeMaxDynamicSharedMemorySize, SMEM_TOTAL);
    void* barp = nullptr;
    cudaGetSymbolAddress(&barp, d_bar);
    cudaMemsetAsync(barp, 0, sizeof(unsigned), 0);

    gemm_xpart<<<dim3(16, 64), 256>>>(Wf, Wi, Wc, Wo, bf, bi, bc, bo, X);
    lstm_recurrent<<<NCTA, 1024, SMEM_TOTAL>>>(Wf, Wi, Wc, Wo, Wy, by, out);
}

// round 15
// speedup vs baseline: 1.0848x; 1.0848x over previous
#include <cuda_runtime.h>
#include <cuda_fp16.h>

#define TSTEPS 2048
#define HID    2048
#define INP    1024
#define NOUT   512
#define ZLEN   (HID + INP)
#define NCTA   147
#define JPER   14
#define GSTRIDE (NCTA * 56)                  /* 8232 floats per timestep */
#define SWS    2056                          /* padded row stride (halfs): conflict-free ldmatrix */

#define SRED_OFF   (56 * SWS * 2)            /* 230272 : sRed[8][64] f32 */
#define SMEM_TOTAL (SRED_OFF + 2048)         /* 232320 <= 232448 */

__device__ __align__(256) float  d_G2[(size_t)TSTEPS * GSTRIDE];
__device__ __align__(256) __half d_h16[(size_t)TSTEPS * HID];   /* h history, fp16, PERMUTED */
__device__ unsigned d_bar;

__device__ __forceinline__ unsigned packh2(float a, float b) {
    __half2 h = __floats2half2_rn(a, b);
    return *(unsigned*)&h;
}
__device__ __forceinline__ float sigmoidf_(float x) { return 1.0f / (1.0f + __expf(-x)); }
__device__ __forceinline__ float tanhf_(float x) {
    float e = __expf(2.0f * x); return 1.0f - 2.0f / (e + 1.0f);
}
__device__ __forceinline__ void ldmx4(unsigned &r0, unsigned &r1, unsigned &r2, unsigned &r3,
                                      unsigned addr) {
    asm volatile("ldmatrix.sync.aligned.m8n8.x4.shared.b16 {%0,%1,%2,%3}, [%4];"
                 : "=r"(r0), "=r"(r1), "=r"(r2), "=r"(r3) : "r"(addr));
}
__device__ __forceinline__ void mma16816(float &c0, float &c1, float &c2, float &c3,
                                         unsigned a0, unsigned a1, unsigned a2, unsigned a3,
                                         unsigned b0, unsigned b1) {
    asm volatile("mma.sync.aligned.m16n8k16.row.col.f32.f16.f16.f32 "
                 "{%0,%1,%2,%3}, {%4,%5,%6,%7}, {%8,%9}, {%0,%1,%2,%3};"
                 : "+f"(c0), "+f"(c1), "+f"(c2), "+f"(c3)
                 : "r"(a0), "r"(a1), "r"(a2), "r"(a3), "r"(b0), "r"(b1));
}

// h-exchange permutation within a 256-half slice: h2 index i (0..127) ->
// position p = 4*((i&7) + 8*(i>>5)) + ((i>>3)&3). Consumer lane L then holds
// comp c = h2 index 32*(L>>3) + 8c + (L&7); at mma k-step s, thread q=lane&3
// needs h2 8s+q (b0) and 8s+4+q (b1): comp = s&3, src lane = q(+4) + 8*(s>>2).
__device__ __forceinline__ int hperm(int i) {
    return 4 * ((i & 7) + 8 * (i >> 5)) + ((i >> 3) & 3);
}

// ---------------- GEMM: x-part preactivations, transposed output layout -------
// d_G2[t*GSTRIDE + bid*56 + jj*4 + g] = W_g[j, H:] . X[t] + b_g[j],  j = bid*14+jj
__global__ __launch_bounds__(256) void gemm_xpart(
    const float* __restrict__ Wf, const float* __restrict__ Wi,
    const float* __restrict__ Wc, const float* __restrict__ Wo,
    const float* __restrict__ bf, const float* __restrict__ bi,
    const float* __restrict__ bc, const float* __restrict__ bo,
    const float* __restrict__ X)
{
    __shared__ float As[16][132];
    __shared__ float Bs[16][132];
    const int bx = blockIdx.x, by = blockIdx.y;
    const int g = by >> 4, jb2 = (by & 15) << 7;
    const float* W  = (g == 0) ? Wf : (g == 1) ? Wi : (g == 2) ? Wc : Wo;
    const float* bb = (g == 0) ? bf : (g == 1) ? bi : (g == 2) ? bc : bo;
    const int tid = threadIdx.x, tx = tid & 15, ty = tid >> 4;
    float acc[8][8];
#pragma unroll
    for (int i = 0; i < 8; ++i)
#pragma unroll
        for (int j = 0; j < 8; ++j) acc[i][j] = 0.0f;
    for (int k0 = 0; k0 < INP; k0 += 16) {
#pragma unroll
        for (int i = 0; i < 2; ++i) {
            int f = tid + i * 256, row = f >> 2, kk = (f & 3) << 2;
            float4 v = *(const float4*)(W + (size_t)(jb2 + row) * ZLEN + HID + k0 + kk);
            As[kk][row] = v.x; As[kk+1][row] = v.y; As[kk+2][row] = v.z; As[kk+3][row] = v.w;
            float4 u = *(const float4*)(X + (size_t)((bx << 7) + row) * INP + k0 + kk);
            Bs[kk][row] = u.x; Bs[kk+1][row] = u.y; Bs[kk+2][row] = u.z; Bs[kk+3][row] = u.w;
        }
        __syncthreads();
#pragma unroll
        for (int k = 0; k < 16; ++k) {
            float a[8], b[8];
            *(float4*)&a[0] = *(const float4*)&As[k][ty*8];
            *(float4*)&a[4] = *(const float4*)&As[k][ty*8+4];
            *(float4*)&b[0] = *(const float4*)&Bs[k][tx*8];
            *(float4*)&b[4] = *(const float4*)&Bs[k][tx*8+4];
#pragma unroll
            for (int ii = 0; ii < 8; ++ii)
#pragma unroll
                for (int jj = 0; jj < 8; ++jj)
                    acc[ii][jj] = fmaf(a[ii], b[jj], acc[ii][jj]);
        }
        __syncthreads();
    }
#pragma unroll
    for (int ii = 0; ii < 8; ++ii) {
        const int j = jb2 + ty * 8 + ii;
        const float bv = __ldg(bb + j);
        const int bidr = j / JPER;
        const int jj   = j - bidr * JPER;
        const int base = bidr * 56 + jj * 4 + g;
#pragma unroll
        for (int q = 0; q < 8; ++q) {
            int t = (bx << 7) + tx * 8 + q;
            d_G2[(size_t)t * GSTRIDE + base] = acc[ii][q] + bv;
        }
    }
}

// ---------------- persistent recurrent kernel --------------------------------
// 147 CTAs x 1024. kg = wid&7 (256-wide k slice), rg = wid>>3 (16 mma rows).
// Gate dots via mma.sync.m16n8k16; B built from permuted h regs (2 shuffles /
// k-step). y row in registers (HFMA2 over the same permuted h). Barrier:
// single poller, one red.release arrival per CTA, fp16 permuted h exchange.
__global__ void __launch_bounds__(1024, 1) lstm_recurrent(
    const float* __restrict__ Wf, const float* __restrict__ Wi,
    const float* __restrict__ Wc, const float* __restrict__ Wo,
    const float* __restrict__ Wy, const float* __restrict__ by,
    float* __restrict__ out)
{
    extern __shared__ char smem[];
    __half* sW   = (__half*)smem;
    float*  sRed = (float*)(smem + SRED_OFF);     // [kg][64]

    const int tid = threadIdx.x, wid = tid >> 5, lane = tid & 31;
    const int kg = wid & 7, rg = wid >> 3;
    const int bid = blockIdx.x, jb = bid * JPER;
    int njj = HID - jb; njj = njj < 0 ? 0 : (njj > JPER ? JPER : njj);
    float* out_y = out;
    float* out_h = out + (size_t)TSTEPS * NOUT;
    unsigned* barp = &d_bar;

    // gate weights -> SMEM fp16 (56 rows x 2048 halfs, row stride SWS=2056)
    for (int c = tid; c < 56 * 256; c += 1024) {
        int gr = c >> 8;
        int k8 = (c & 255) << 3;
        int jj = gr >> 2, g = gr & 3;
        uint4 u = {0u, 0u, 0u, 0u};
        if (jj < njj) {
            const float* W = (g == 0) ? Wf : (g == 1) ? Wi : (g == 2) ? Wc : Wo;
            const float* p = W + (size_t)(jb + jj) * ZLEN + k8;
            float4 v0 = *(const float4*)p;
            float4 v1 = *(const float4*)(p + 4);
            u.x = packh2(v0.x, v0.y); u.y = packh2(v0.z, v0.w);
            u.z = packh2(v1.x, v1.y); u.w = packh2(v1.z, v1.w);
        }
        *(uint4*)(sW + gr * SWS + k8) = u;
    }

    // y-row weights -> registers (row bid*4 + rg), fp16, SAME permutation as h
    unsigned wy2[4] = {0u, 0u, 0u, 0u};
    if (bid < 128) {
        const float* prow = Wy + (size_t)(bid * 4 + rg) * HID;
#pragma unroll
        for (int c = 0; c < 4; ++c) {
            int i_c = kg * 128 + 32 * (lane >> 3) + 8 * c + (lane & 7);  // global h2 idx
            float2 v = *(const float2*)(prow + 2 * i_c);
            wy2[c] = packh2(v.x, v.y);
        }
    }

    // per-lane ldmatrix base address (shared-space u32), advances 32B per k-step
    unsigned sw_u = (unsigned)__cvta_generic_to_shared(sW);
    unsigned a_base;
    {
        int li = lane & 7, gsel = lane >> 3;
        int row_in_tile = ((gsel & 1) << 3) + li;
        if (rg == 3 && row_in_tile >= 8) row_in_tile -= 8;   // dup: only 8 real rows
        int k_half = (gsel >> 1) << 3;                        // 0 or 8
        a_base = sw_u + (unsigned)(((rg * 16 + row_in_tile) * SWS + kg * 256 + k_half) * 2);
    }

    float c_st = 0.0f;                       // warp 0, lane = jj
    float byv = 0.0f;
    if (wid == 0 && lane >= 16 && lane < 20 && bid < 128)
        byv = __ldg(by + bid * 4 + (lane - 16));

    for (int t = 0; t <= TSTEPS; ++t) {
        if (t > 0 && wid == 0 && lane == 0) {     // single poller per CTA
            const unsigned target = (unsigned)t * (unsigned)NCTA;
            unsigned v;
            do {
                asm volatile("ld.acquire.gpu.global.u32 %0, [%1];"
                             : "=r"(v) : "l"(barp) : "memory");
            } while (v < target);
        }
        __syncthreads();                          // S1: release CTA; orders sRed WAR

        // warp 0: prefetch this step's G early (long latency cover)
        float4 gv = {0.f, 0.f, 0.f, 0.f};
        if (wid == 0 && lane < JPER && t < TSTEPS)
            gv = __ldcg((const float4*)(d_G2 + (size_t)t * GSTRIDE + bid * 56 + lane * 4));

        // h(t-1) slice -> regs: one LDG.128 from permuted fp16 history.
        // hv component c = h2 index 32*(lane>>3) + 8c + (lane&7) of this slice.
        unsigned hvc[4] = {0u, 0u, 0u, 0u};
        if (t > 0) {
            uint4 hv = __ldcg((const uint4*)(d_h16 + (size_t)(t - 1) * HID + kg * 256 + lane * 8));
            hvc[0] = hv.x; hvc[1] = hv.y; hvc[2] = hv.z; hvc[3] = hv.w;
        }

        // 16 k-steps of m16n8k16, two interleaved accumulators
        float cA0 = 0.f, cA1 = 0.f, cA2 = 0.f, cA3 = 0.f;
        float cB0 = 0.f, cB1 = 0.f, cB2 = 0.f, cB3 = 0.f;
        unsigned aaddr = a_base;
        const int q = lane & 3;
#pragma unroll
        for (int s = 0; s < 16; ++s) {
            unsigned a0, a1, a2, a3;
            ldmx4(a0, a1, a2, a3, aaddr);
            aaddr += 32;
            int srcb = q + 8 * (s >> 2);
            unsigned b0 = __shfl_sync(0xFFFFFFFFu, hvc[s & 3], srcb);
            unsigned b1 = __shfl_sync(0xFFFFFFFFu, hvc[s & 3], srcb + 4);
            if (s & 1) mma16816(cB0, cB1, cB2, cB3, a0, a1, a2, a3, b0, b1);
            else       mma16816(cA0, cA1, cA2, cA3, a0, a1, a2, a3, b0, b1);
        }
        cA0 += cB0; cA2 += cB2;                   // only col 0 needed (c0, c2)

        // y row: HFMA2 on permuted h regs (order-independent dot) + reduce
        float ysum;
        {
            __half2 acc = __hmul2(*(__half2*)&wy2[0], *(__half2*)&hvc[0]);
            acc = __hfma2(*(__half2*)&wy2[1], *(__half2*)&hvc[1], acc);
            acc = __hfma2(*(__half2*)&wy2[2], *(__half2*)&hvc[2], acc);
            acc = __hfma2(*(__half2*)&wy2[3], *(__half2*)&hvc[3], acc);
            float2 f = __half22float2(acc);
            ysum = f.x + f.y;
#pragma unroll
            for (int off = 16; off > 0; off >>= 1)
                ysum += __shfl_xor_sync(0xFFFFFFFFu, ysum, off);
        }

        // store gate partials (col 0 of D): lane&3==0 lanes hold rows
        if ((lane & 3) == 0) {
            int r0 = rg * 16 + (lane >> 2);       // rows 0..7 of tile
            sRed[kg * 64 + r0] = cA0;
            if (rg < 3) sRed[kg * 64 + r0 + 8] = cA2;   // rows 8..15 (rg==3: dup, skip)
        }
        if (lane == 0) sRed[kg * 64 + 56 + rg] = ysum;

        __syncthreads();                          // S2

        if (wid == 0) {
            if (t < TSTEPS) {
                float hvout = 0.0f;
                const bool act = (lane < njj);
                if (act) {
                    float4 a = *(const float4*)(sRed + 0 * 64 + lane * 4);
#pragma unroll
                    for (int k2 = 1; k2 < 8; ++k2) {
                        float4 b = *(const float4*)(sRed + k2 * 64 + lane * 4);
                        a.x += b.x; a.y += b.y; a.z += b.z; a.w += b.w;
                    }
                    a.x += gv.x; a.y += gv.y; a.z += gv.z; a.w += gv.w;
                    float fg = sigmoidf_(a.x);
                    float ig = sigmoidf_(a.y);
                    float cc = tanhf_(a.z);
                    float og = sigmoidf_(a.w);
                    c_st = fg * c_st + ig * cc;
                    hvout = og * tanhf_(c_st);
                    // exchange store, PERMUTED layout
                    int j  = jb + lane;
                    int sl = j >> 8;              // slice (kg of consumers)
                    int l  = j & 255;             // half within slice
                    int ip = hperm(l >> 1);       // permuted h2 position
                    d_h16[(size_t)t * HID + sl * 256 + ip * 2 + (l & 1)] = __float2half(hvout);
                }
                __syncwarp();                     // warp-scope fence: order lane stores
                if (lane == 0)                    // ONE arrival per CTA
                    asm volatile("red.release.gpu.global.add.u32 [%0], %1;"
                                 :: "l"(barp), "r"(1u) : "memory");
                if (act)
                    out_h[(size_t)t * HID + jb + lane] = hvout;   // fp32 output, off-path
            }
            // y output off the critical path (after publish)
            if (t >= 1 && bid < 128 && lane >= 16 && lane < 20) {
                float s = 0.0f;
#pragma unroll
                for (int k2 = 0; k2 < 8; ++k2) s += sRed[k2 * 64 + 56 + (lane - 16)];
                out_y[(size_t)(t - 1) * NOUT + bid * 4 + (lane - 16)] = s + byv;
            }
        }
    }
}

extern "C" void kernel_launch(void* const* d_in, const int* in_sizes, int n_in,
                              void* d_out, int out_size) {
    (void)in_sizes; (void)n_in; (void)out_size;
    const float* X  = (const float*)d_in[0];
    const float* Wf = (const float*)d_in[1];
    const float* bf = (const float*)d_in[2];
    const float* Wi = (const float*)d_in[3];
    const float* bi = (const float*)d_in[4];
    const float* Wc = (const float*)d_in[5];
    const float* bc = (const float*)d_in[6];
    const float* Wo = (const float*)d_in[7];
    const float* bo = (const float*)d_in[8];
    const float* Wy = (const float*)d_in[9];
    const float* by = (const float*)d_in[10];
    float* out = (float*)d_out;

    cudaFuncSetAttribute(lstm_recurrent,
                         cudaFuncAttributeMaxDynamicSharedMemorySize, SMEM_TOTAL);
    void* barp = nullptr;
    cudaGetSymbolAddress(&barp, d_bar);
    cudaMemsetAsync(barp, 0, sizeof(unsigned), 0);

    gemm_xpart<<<dim3(16, 64), 256>>>(Wf, Wi, Wc, Wo, bf, bi, bc, bo, X);
    lstm_recurrent<<<NCTA, 1024, SMEM_TOTAL>>>(Wf, Wi, Wc, Wo, Wy, by, out);
}